// round 11
// baseline (speedup 1.0000x reference)
#include <cuda_runtime.h>
#include <cstdint>

#define N_NODES 100000
#define N_EDGES 3200000
#define E4 (N_EDGES / 4)

#define NBLK 6            // CTAs per SM (register-file guaranteed: 6*256*42 <= 65536)
#define GRID (148 * NBLK) // 888 CTAs, all co-resident in wave 1
#define TPB  256
#define NTHREADS (GRID * TPB)
#define N_PHASES 5

// Scratch (device globals — zero-initialized at module load; no allocation).
__device__ float  g_deg[N_NODES];    // consume-and-reset each replay
__device__ float  g_dinv[N_NODES];
__device__ float2 g_xs[N_NODES];
__device__ float2 g_agg1[N_NODES];
__device__ float2 g_ps[N_NODES];
__device__ float2 g_agg2[N_NODES];
__device__ unsigned g_bar;           // barrier counter; self-resets at final barrier

__device__ __forceinline__ void red_add_f2(float2* addr, float2 v) {
    asm volatile("red.global.add.v2.f32 [%0], {%1, %2};"
                 :: "l"(addr), "f"(v.x), "f"(v.y) : "memory");
}
__device__ __forceinline__ void red_add_f(float* addr, float v) {
    asm volatile("red.global.add.f32 [%0], %1;"
                 :: "l"(addr), "f"(v) : "memory");
}

// Grid barrier. All GRID CTAs are co-resident (see NBLK math), so spinning is
// deadlock-free. __threadfence (gpu scope) publishes writes + invalidates L1D.
// The FINAL barrier's last arriver resets the counter to 0 for the next graph
// replay; spinners treat v==0 as released (v >= 4*GRID+1 during final arrival,
// so 0 is unambiguous).
__device__ __forceinline__ void gbar(int phase) {
    __threadfence();
    __syncthreads();
    if (threadIdx.x == 0) {
        const unsigned target = (unsigned)phase * GRID;
        unsigned old = atomicAdd(&g_bar, 1u);
        if (phase == N_PHASES && old == target - 1u) {
            __threadfence();
            g_bar = 0u;                          // last arriver: reset for next replay
        } else {
            unsigned v;
            do {
                v = *(volatile unsigned*)&g_bar;
                if (v >= target || (phase == N_PHASES && v == 0u)) break;
                __nanosleep(64);
            } while (true);
        }
    }
    __syncthreads();
}

// ---------------------------------------------------------------------------
__global__ void __launch_bounds__(TPB, NBLK) k_fused(
    const float2* __restrict__ x2,
    const int4*   __restrict__ src4,
    const int4*   __restrict__ dst4,
    const float*  __restrict__ W1,   // [2,16]
    const float*  __restrict__ b1,   // [16]
    const float*  __restrict__ W2,   // [16,2]
    const float*  __restrict__ b2,   // [2]
    float2*       __restrict__ out2)
{
    const int tid = blockIdx.x * TPB + threadIdx.x;

    // ---- Phase 1: degree ----
    for (int t = tid; t < E4; t += NTHREADS) {
        int4 d = dst4[t];
        red_add_f(&g_deg[d.x], 1.0f);
        red_add_f(&g_deg[d.y], 1.0f);
        red_add_f(&g_deg[d.z], 1.0f);
        red_add_f(&g_deg[d.w], 1.0f);
    }
    gbar(1);

    // ---- Phase 2: dinv + premultiplied features + self-loop seed ----
    for (int i = tid; i < N_NODES; i += NTHREADS) {
        float dg = g_deg[i];
        g_deg[i] = 0.f;                          // reset for next replay
        float di = rsqrtf(dg + 1.0f);            // +1 self-loop
        g_dinv[i] = di;
        float2 xi = x2[i];
        float2 xs = make_float2(xi.x * di, xi.y * di);
        g_xs[i]   = xs;
        g_agg1[i] = xs;                          // self-loop seed
    }
    gbar(2);

    // ---- Phase 3: scatter layer 1 ----
    for (int t = tid; t < E4; t += NTHREADS) {
        int4 s = src4[t];
        int4 d = dst4[t];
        float2 v0 = __ldg(&g_xs[s.x]);
        float2 v1 = __ldg(&g_xs[s.y]);
        float2 v2 = __ldg(&g_xs[s.z]);
        float2 v3 = __ldg(&g_xs[s.w]);
        red_add_f2(&g_agg1[d.x], v0);
        red_add_f2(&g_agg1[d.y], v1);
        red_add_f2(&g_agg1[d.z], v2);
        red_add_f2(&g_agg1[d.w], v3);
    }
    gbar(3);

    // ---- Phase 4: MLP (norm -> W1 -> relu -> W2 -> premult) ----
    // Weights streamed via __ldg with unroll 1 to keep regs under the
    // launch_bounds cap (no 80-float register arrays, no spills).
    for (int i = tid; i < N_NODES; i += NTHREADS) {
        float di = g_dinv[i];
        float2 t = g_agg1[i];
        float ax = t.x * di, ay = t.y * di;
        float px = 0.f, py = 0.f;
#pragma unroll 1
        for (int j = 0; j < 16; j++) {
            float h = ax * __ldg(&W1[j]) + ay * __ldg(&W1[16 + j]) + __ldg(&b1[j]);
            h = fmaxf(h, 0.f);
            px += h * __ldg(&W2[2 * j]);
            py += h * __ldg(&W2[2 * j + 1]);
        }
        float2 ps = make_float2(px * di, py * di);
        g_ps[i]   = ps;
        g_agg2[i] = ps;                          // self-loop seed
    }
    gbar(4);

    // ---- Phase 5: scatter layer 2 ----
    for (int t = tid; t < E4; t += NTHREADS) {
        int4 s = src4[t];
        int4 d = dst4[t];
        float2 v0 = __ldg(&g_ps[s.x]);
        float2 v1 = __ldg(&g_ps[s.y]);
        float2 v2 = __ldg(&g_ps[s.z]);
        float2 v3 = __ldg(&g_ps[s.w]);
        red_add_f2(&g_agg2[d.x], v0);
        red_add_f2(&g_agg2[d.y], v1);
        red_add_f2(&g_agg2[d.z], v2);
        red_add_f2(&g_agg2[d.w], v3);
    }
    gbar(5);                                     // final: also resets g_bar

    // ---- Phase 6: bias + log_softmax ----
    for (int i = tid; i < N_NODES; i += NTHREADS) {
        float di = g_dinv[i];
        float2 t = g_agg2[i];
        float zx = t.x * di + __ldg(&b2[0]);
        float zy = t.y * di + __ldg(&b2[1]);
        float m = fmaxf(zx, zy);
        float l = m + __logf(__expf(zx - m) + __expf(zy - m));
        out2[i] = make_float2(zx - l, zy - l);
    }
}

// ---------------------------------------------------------------------------
extern "C" void kernel_launch(void* const* d_in, const int* in_sizes, int n_in,
                              void* d_out, int out_size) {
    const float* x  = (const float*)d_in[0];   // [N,2]
    const int*   ei = (const int*)d_in[1];     // [2,E] int32
    const float* W1 = (const float*)d_in[2];
    const float* b1 = (const float*)d_in[3];
    const float* W2 = (const float*)d_in[4];
    const float* b2 = (const float*)d_in[5];

    const int4* src4 = (const int4*)ei;
    const int4* dst4 = (const int4*)(ei + N_EDGES);
    const float2* x2 = (const float2*)x;
    float2* out2 = (float2*)d_out;

    k_fused<<<GRID, TPB>>>(x2, src4, dst4, W1, b1, W2, b2, out2);
}

// round 12
// speedup vs baseline: 1.1008x; 1.1008x over previous
#include <cuda_runtime.h>
#include <cstdint>

#define N_NODES 100000
#define N_EDGES 3200000
#define E4 (N_EDGES / 4)

#define NBLK 6            // CTAs/SM; regs<=42 guaranteed by launch_bounds
#define GRID (148 * NBLK) // 888 CTAs, all co-resident in wave 1
#define TPB  256
#define NTHREADS (GRID * TPB)
#define N_PHASES 5

#define CHUNK   TPB                       // int4-groups per ticket (1024 edges)
#define NCHUNKS ((E4 + CHUNK - 1) / CHUNK) // 3125

// Scratch (device globals — zero-initialized at module load; no allocation).
__device__ float  g_deg[N_NODES];    // consume-and-reset each replay
__device__ float  g_dinv[N_NODES];
__device__ float2 g_xs[N_NODES];
__device__ float2 g_agg1[N_NODES];
__device__ float2 g_ps[N_NODES];
__device__ float2 g_agg2[N_NODES];
__device__ unsigned g_bar;           // barrier counter; reset by final barrier
__device__ unsigned g_tick[3];       // work-stealing tickets: deg, scat1, scat2

__device__ __forceinline__ void red_add_f2(float2* addr, float2 v) {
    asm volatile("red.global.add.v2.f32 [%0], {%1, %2};"
                 :: "l"(addr), "f"(v.x), "f"(v.y) : "memory");
}
__device__ __forceinline__ void red_add_f(float* addr, float v) {
    asm volatile("red.global.add.f32 [%0], %1;"
                 :: "l"(addr), "f"(v) : "memory");
}

// Grid barrier (all GRID CTAs co-resident -> deadlock-free). gpu-scope fence
// publishes writes and invalidates L1D. The FINAL barrier's last arriver
// resets tickets + counter for the next graph replay; spinners accept v==0
// as released (v >= 4*GRID+1 during the final arrival window, unambiguous).
__device__ __forceinline__ void gbar(int phase) {
    __threadfence();
    __syncthreads();
    if (threadIdx.x == 0) {
        const unsigned target = (unsigned)phase * GRID;
        unsigned old = atomicAdd(&g_bar, 1u);
        if (phase == N_PHASES && old == target - 1u) {
            g_tick[0] = 0u; g_tick[1] = 0u; g_tick[2] = 0u;
            __threadfence();
            atomicExch(&g_bar, 0u);              // release
        } else {
            unsigned v;
            do {
                v = *(volatile unsigned*)&g_bar;
                if (v >= target || (phase == N_PHASES && v == 0u)) break;
                __nanosleep(64);
            } while (true);
        }
    }
    __syncthreads();
}

// ---------------------------------------------------------------------------
__global__ void __launch_bounds__(TPB, NBLK) k_fused(
    const float2* __restrict__ x2,
    const int4*   __restrict__ src4,
    const int4*   __restrict__ dst4,
    const float*  __restrict__ W1,   // [2,16]
    const float*  __restrict__ b1,   // [16]
    const float*  __restrict__ W2,   // [16,2]
    const float*  __restrict__ b2,   // [2]
    float2*       __restrict__ out2)
{
    const int tid = blockIdx.x * TPB + threadIdx.x;
    __shared__ unsigned s_chunk;

    // ---- Phase 1: degree (work-stealing) ----
    for (;;) {
        if (threadIdx.x == 0) s_chunk = atomicAdd(&g_tick[0], 1u);
        __syncthreads();
        unsigned c = s_chunk;
        __syncthreads();
        if (c >= NCHUNKS) break;
        int t = (int)c * CHUNK + threadIdx.x;
        if (t < E4) {
            int4 d = dst4[t];
            red_add_f(&g_deg[d.x], 1.0f);
            red_add_f(&g_deg[d.y], 1.0f);
            red_add_f(&g_deg[d.z], 1.0f);
            red_add_f(&g_deg[d.w], 1.0f);
        }
    }
    gbar(1);

    // ---- Phase 2: dinv + premultiplied features + self-loop seed (static) ----
    for (int i = tid; i < N_NODES; i += NTHREADS) {
        float dg = g_deg[i];
        g_deg[i] = 0.f;                          // reset for next replay
        float di = rsqrtf(dg + 1.0f);            // +1 self-loop
        g_dinv[i] = di;
        float2 xi = x2[i];
        float2 xs = make_float2(xi.x * di, xi.y * di);
        g_xs[i]   = xs;
        g_agg1[i] = xs;
    }
    gbar(2);

    // ---- Phase 3: scatter layer 1 (work-stealing) ----
    for (;;) {
        if (threadIdx.x == 0) s_chunk = atomicAdd(&g_tick[1], 1u);
        __syncthreads();
        unsigned c = s_chunk;
        __syncthreads();
        if (c >= NCHUNKS) break;
        int t = (int)c * CHUNK + threadIdx.x;
        if (t < E4) {
            int4 s = src4[t];
            int4 d = dst4[t];
            float2 v0 = __ldg(&g_xs[s.x]);
            float2 v1 = __ldg(&g_xs[s.y]);
            float2 v2 = __ldg(&g_xs[s.z]);
            float2 v3 = __ldg(&g_xs[s.w]);
            red_add_f2(&g_agg1[d.x], v0);
            red_add_f2(&g_agg1[d.y], v1);
            red_add_f2(&g_agg1[d.z], v2);
            red_add_f2(&g_agg1[d.w], v3);
        }
    }
    gbar(3);

    // ---- Phase 4: MLP (static; weights streamed, unroll 1 to cap regs) ----
    for (int i = tid; i < N_NODES; i += NTHREADS) {
        float di = g_dinv[i];
        float2 t = g_agg1[i];
        float ax = t.x * di, ay = t.y * di;
        float px = 0.f, py = 0.f;
#pragma unroll 1
        for (int j = 0; j < 16; j++) {
            float h = ax * __ldg(&W1[j]) + ay * __ldg(&W1[16 + j]) + __ldg(&b1[j]);
            h = fmaxf(h, 0.f);
            px += h * __ldg(&W2[2 * j]);
            py += h * __ldg(&W2[2 * j + 1]);
        }
        float2 ps = make_float2(px * di, py * di);
        g_ps[i]   = ps;
        g_agg2[i] = ps;
    }
    gbar(4);

    // ---- Phase 5: scatter layer 2 (work-stealing) ----
    for (;;) {
        if (threadIdx.x == 0) s_chunk = atomicAdd(&g_tick[2], 1u);
        __syncthreads();
        unsigned c = s_chunk;
        __syncthreads();
        if (c >= NCHUNKS) break;
        int t = (int)c * CHUNK + threadIdx.x;
        if (t < E4) {
            int4 s = src4[t];
            int4 d = dst4[t];
            float2 v0 = __ldg(&g_ps[s.x]);
            float2 v1 = __ldg(&g_ps[s.y]);
            float2 v2 = __ldg(&g_ps[s.z]);
            float2 v3 = __ldg(&g_ps[s.w]);
            red_add_f2(&g_agg2[d.x], v0);
            red_add_f2(&g_agg2[d.y], v1);
            red_add_f2(&g_agg2[d.z], v2);
            red_add_f2(&g_agg2[d.w], v3);
        }
    }
    gbar(5);                                     // final: resets tickets + bar

    // ---- Phase 6: bias + log_softmax (static) ----
    for (int i = tid; i < N_NODES; i += NTHREADS) {
        float di = g_dinv[i];
        float2 t = g_agg2[i];
        float zx = t.x * di + __ldg(&b2[0]);
        float zy = t.y * di + __ldg(&b2[1]);
        float m = fmaxf(zx, zy);
        float l = m + __logf(__expf(zx - m) + __expf(zy - m));
        out2[i] = make_float2(zx - l, zy - l);
    }
}

// ---------------------------------------------------------------------------
extern "C" void kernel_launch(void* const* d_in, const int* in_sizes, int n_in,
                              void* d_out, int out_size) {
    const float* x  = (const float*)d_in[0];   // [N,2]
    const int*   ei = (const int*)d_in[1];     // [2,E] int32
    const float* W1 = (const float*)d_in[2];
    const float* b1 = (const float*)d_in[3];
    const float* W2 = (const float*)d_in[4];
    const float* b2 = (const float*)d_in[5];

    const int4* src4 = (const int4*)ei;
    const int4* dst4 = (const int4*)(ei + N_EDGES);
    const float2* x2 = (const float2*)x;
    float2* out2 = (float2*)d_out;

    k_fused<<<GRID, TPB>>>(x2, src4, dst4, W1, b1, W2, b2, out2);
}

// round 13
// speedup vs baseline: 1.2399x; 1.1264x over previous
#include <cuda_runtime.h>
#include <cstdint>

#define N_NODES 100000
#define N_EDGES 3200000
#define E4 (N_EDGES / 4)

// Scratch (device globals — zero-initialized at module load; no allocation).
// g_deg is consume-and-reset: k_degree accumulates, k_pre1 reads then zeroes,
// so every graph replay starts from 0 without a memset node.
__device__ float  g_deg[N_NODES];
__device__ float  g_dinv[N_NODES];
__device__ float2 g_xs[N_NODES];     // x[i] * dinv[i]
__device__ float2 g_agg1[N_NODES];
__device__ float2 g_ps[N_NODES];     // (h1@W2)[i] * dinv[i]
__device__ float2 g_agg2[N_NODES];

__device__ __forceinline__ void red_add_f2(float2* addr, float2 v) {
    asm volatile("red.global.add.v2.f32 [%0], {%1, %2};"
                 :: "l"(addr), "f"(v.x), "f"(v.y) : "memory");
}
__device__ __forceinline__ void red_add_f(float* addr, float v) {
    asm volatile("red.global.add.f32 [%0], %1;"
                 :: "l"(addr), "f"(v) : "memory");
}

// ---------------------------------------------------------------------------
__global__ void k_degree(const int4* __restrict__ dst4) {
    int t = blockIdx.x * blockDim.x + threadIdx.x;
    if (t < E4) {
        int4 d = dst4[t];
        red_add_f(&g_deg[d.x], 1.0f);
        red_add_f(&g_deg[d.y], 1.0f);
        red_add_f(&g_deg[d.z], 1.0f);
        red_add_f(&g_deg[d.w], 1.0f);
    }
}

// 1 node per thread; consumes and resets g_deg.
__global__ void k_pre1(const float2* __restrict__ x2) {
    int i = blockIdx.x * blockDim.x + threadIdx.x;
    if (i < N_NODES) {
        float dg = g_deg[i];
        g_deg[i] = 0.f;                       // reset for next replay
        float di = rsqrtf(dg + 1.0f);         // +1 self-loop
        g_dinv[i] = di;
        float2 xi = x2[i];
        float2 xs = make_float2(xi.x * di, xi.y * di);
        g_xs[i]   = xs;
        g_agg1[i] = xs;                       // self-loop seed
    }
}

__global__ void k_scatter1(const int4* __restrict__ src4,
                           const int4* __restrict__ dst4) {
    int t = blockIdx.x * blockDim.x + threadIdx.x;
    if (t < E4) {
        int4 s = src4[t];
        int4 d = dst4[t];
        float2 v0 = __ldg(&g_xs[s.x]);
        float2 v1 = __ldg(&g_xs[s.y]);
        float2 v2 = __ldg(&g_xs[s.z]);
        float2 v3 = __ldg(&g_xs[s.w]);
        red_add_f2(&g_agg1[d.x], v0);
        red_add_f2(&g_agg1[d.y], v1);
        red_add_f2(&g_agg1[d.z], v2);
        red_add_f2(&g_agg1[d.w], v3);
    }
}

// 1 node per thread; weights/bias hoisted via full unroll (CSE'd uniform loads).
__global__ void k_mid(const float* __restrict__ W1,   // [2,16]
                      const float* __restrict__ b1,   // [16]
                      const float* __restrict__ W2) { // [16,2]
    int i = blockIdx.x * blockDim.x + threadIdx.x;
    if (i >= N_NODES) return;
    float di = g_dinv[i];
    float2 t = g_agg1[i];
    float ax = t.x * di, ay = t.y * di;
    float px = 0.0f, py = 0.0f;
#pragma unroll
    for (int j = 0; j < 16; j++) {
        float h = ax * __ldg(&W1[j]) + ay * __ldg(&W1[16 + j]) + __ldg(&b1[j]);
        h = fmaxf(h, 0.0f);
        px += h * __ldg(&W2[2 * j]);
        py += h * __ldg(&W2[2 * j + 1]);
    }
    float2 ps = make_float2(px * di, py * di);
    g_ps[i]   = ps;
    g_agg2[i] = ps;                           // self-loop seed
}

__global__ void k_scatter2(const int4* __restrict__ src4,
                           const int4* __restrict__ dst4) {
    int t = blockIdx.x * blockDim.x + threadIdx.x;
    if (t < E4) {
        int4 s = src4[t];
        int4 d = dst4[t];
        float2 v0 = __ldg(&g_ps[s.x]);
        float2 v1 = __ldg(&g_ps[s.y]);
        float2 v2 = __ldg(&g_ps[s.z]);
        float2 v3 = __ldg(&g_ps[s.w]);
        red_add_f2(&g_agg2[d.x], v0);
        red_add_f2(&g_agg2[d.y], v1);
        red_add_f2(&g_agg2[d.z], v2);
        red_add_f2(&g_agg2[d.w], v3);
    }
}

__global__ void k_out(const float* __restrict__ b2, float2* __restrict__ out2) {
    int i = blockIdx.x * blockDim.x + threadIdx.x;
    if (i >= N_NODES) return;
    float di = g_dinv[i];
    float2 t = g_agg2[i];
    float zx = t.x * di + __ldg(&b2[0]);
    float zy = t.y * di + __ldg(&b2[1]);
    float m = fmaxf(zx, zy);
    float l = m + __logf(__expf(zx - m) + __expf(zy - m));
    out2[i] = make_float2(zx - l, zy - l);
}

// ---------------------------------------------------------------------------
extern "C" void kernel_launch(void* const* d_in, const int* in_sizes, int n_in,
                              void* d_out, int out_size) {
    const float* x  = (const float*)d_in[0];   // [N,2]
    const int*   ei = (const int*)d_in[1];     // [2,E] int32
    const float* W1 = (const float*)d_in[2];
    const float* b1 = (const float*)d_in[3];
    const float* W2 = (const float*)d_in[4];
    const float* b2 = (const float*)d_in[5];

    const int4* src4 = (const int4*)ei;
    const int4* dst4 = (const int4*)(ei + N_EDGES);
    const float2* x2 = (const float2*)x;
    float2* out2 = (float2*)d_out;

    const int T = 256;
    const int gN  = (N_NODES + T - 1) / T;
    const int gE4 = (E4 + T - 1) / T;

    k_degree<<<gE4, T>>>(dst4);
    k_pre1<<<gN, T>>>(x2);
    k_scatter1<<<gE4, T>>>(src4, dst4);
    k_mid<<<gN, T>>>(W1, b1, W2);
    k_scatter2<<<gE4, T>>>(src4, dst4);
    k_out<<<gN, T>>>(b2, out2);
}

// round 14
// speedup vs baseline: 1.2679x; 1.0225x over previous
#include <cuda_runtime.h>
#include <cstdint>

#define N_NODES 100000
#define N_EDGES 3200000
#define E4 (N_EDGES / 4)

// Scratch (device globals — zero-initialized at module load; no allocation).
__device__ float  g_deg[N_NODES];    // consume-and-reset each replay
__device__ float  g_dinv[N_NODES];
__device__ float2 g_xs[N_NODES];     // x[i] * dinv[i]
__device__ float2 g_agg1[N_NODES];
__device__ float2 g_ps[N_NODES];     // (h1@W2)[i] * dinv[i]
__device__ float2 g_agg2[N_NODES];

__device__ __forceinline__ void red_add_f2(float2* addr, float2 v) {
    asm volatile("red.global.add.v2.f32 [%0], {%1, %2};"
                 :: "l"(addr), "f"(v.x), "f"(v.y) : "memory");
}
__device__ __forceinline__ void red_add_f(float* addr, float v) {
    asm volatile("red.global.add.f32 [%0], %1;"
                 :: "l"(addr), "f"(v) : "memory");
}

// ---------------------------------------------------------------------------
// PDL pattern: trigger at block top (successor may launch into our drain ramp),
// independent input loads BEFORE griddepsync, dependent reads after.
// griddepcontrol.wait requires full predecessor completion + visibility, so
// trigger placement affects performance only, never correctness.

__global__ void k_degree(const int4* __restrict__ dst4) {
    cudaTriggerProgrammaticLaunchCompletion();
    int t = blockIdx.x * blockDim.x + threadIdx.x;
    if (t < E4) {
        int4 d = dst4[t];                         // input: independent
        cudaGridDependencySynchronize();          // no-op for first node; cheap
        red_add_f(&g_deg[d.x], 1.0f);
        red_add_f(&g_deg[d.y], 1.0f);
        red_add_f(&g_deg[d.z], 1.0f);
        red_add_f(&g_deg[d.w], 1.0f);
    }
}

__global__ void k_pre1(const float2* __restrict__ x2) {
    cudaTriggerProgrammaticLaunchCompletion();
    int i = blockIdx.x * blockDim.x + threadIdx.x;
    float2 xi = make_float2(0.f, 0.f);
    if (i < N_NODES) xi = x2[i];                  // input: independent
    cudaGridDependencySynchronize();              // wait for k_degree
    if (i < N_NODES) {
        float dg = g_deg[i];
        g_deg[i] = 0.f;                           // reset for next replay
        float di = rsqrtf(dg + 1.0f);             // +1 self-loop
        g_dinv[i] = di;
        float2 xs = make_float2(xi.x * di, xi.y * di);
        g_xs[i]   = xs;
        g_agg1[i] = xs;                           // self-loop seed
    }
}

__global__ void k_scatter1(const int4* __restrict__ src4,
                           const int4* __restrict__ dst4) {
    cudaTriggerProgrammaticLaunchCompletion();
    int t = blockIdx.x * blockDim.x + threadIdx.x;
    if (t < E4) {
        int4 s = src4[t];                         // inputs: independent
        int4 d = dst4[t];
        cudaGridDependencySynchronize();          // wait for k_pre1
        float2 v0 = __ldg(&g_xs[s.x]);
        float2 v1 = __ldg(&g_xs[s.y]);
        float2 v2 = __ldg(&g_xs[s.z]);
        float2 v3 = __ldg(&g_xs[s.w]);
        red_add_f2(&g_agg1[d.x], v0);
        red_add_f2(&g_agg1[d.y], v1);
        red_add_f2(&g_agg1[d.z], v2);
        red_add_f2(&g_agg1[d.w], v3);
    } else {
        cudaGridDependencySynchronize();
    }
}

// Weights via float4 (20 LDG.128 instead of 80 LDG.32), loaded pre-sync.
__global__ void k_mid(const float4* __restrict__ W1v,   // [2,16] -> 8 float4
                      const float4* __restrict__ b1v,   // [16]   -> 4 float4
                      const float4* __restrict__ W2v) { // [16,2] -> 8 float4
    cudaTriggerProgrammaticLaunchCompletion();
    int i = blockIdx.x * blockDim.x + threadIdx.x;

    float4 w1a[4], w1b[4], bb[4], w2[8];
#pragma unroll
    for (int g = 0; g < 4; g++) {
        w1a[g] = __ldg(&W1v[g]);        // row0[4g..4g+3]
        w1b[g] = __ldg(&W1v[4 + g]);    // row1[4g..4g+3]
        bb[g]  = __ldg(&b1v[g]);
        w2[2 * g]     = __ldg(&W2v[2 * g]);      // (j=4g,c0),(4g,c1),(4g+1,c0),(4g+1,c1)
        w2[2 * g + 1] = __ldg(&W2v[2 * g + 1]);  // j=4g+2, 4g+3
    }
    cudaGridDependencySynchronize();              // wait for k_scatter1
    if (i >= N_NODES) return;

    float di = g_dinv[i];
    float2 t = g_agg1[i];
    float ax = t.x * di, ay = t.y * di;
    float px = 0.f, py = 0.f;
#pragma unroll
    for (int g = 0; g < 4; g++) {
        float h0 = fmaxf(ax * w1a[g].x + ay * w1b[g].x + bb[g].x, 0.f);
        float h1 = fmaxf(ax * w1a[g].y + ay * w1b[g].y + bb[g].y, 0.f);
        float h2 = fmaxf(ax * w1a[g].z + ay * w1b[g].z + bb[g].z, 0.f);
        float h3 = fmaxf(ax * w1a[g].w + ay * w1b[g].w + bb[g].w, 0.f);
        px += h0 * w2[2 * g].x + h1 * w2[2 * g].z
            + h2 * w2[2 * g + 1].x + h3 * w2[2 * g + 1].z;
        py += h0 * w2[2 * g].y + h1 * w2[2 * g].w
            + h2 * w2[2 * g + 1].y + h3 * w2[2 * g + 1].w;
    }
    float2 ps = make_float2(px * di, py * di);
    g_ps[i]   = ps;
    g_agg2[i] = ps;                               // self-loop seed
}

__global__ void k_scatter2(const int4* __restrict__ src4,
                           const int4* __restrict__ dst4) {
    cudaTriggerProgrammaticLaunchCompletion();
    int t = blockIdx.x * blockDim.x + threadIdx.x;
    if (t < E4) {
        int4 s = src4[t];
        int4 d = dst4[t];
        cudaGridDependencySynchronize();          // wait for k_mid
        float2 v0 = __ldg(&g_ps[s.x]);
        float2 v1 = __ldg(&g_ps[s.y]);
        float2 v2 = __ldg(&g_ps[s.z]);
        float2 v3 = __ldg(&g_ps[s.w]);
        red_add_f2(&g_agg2[d.x], v0);
        red_add_f2(&g_agg2[d.y], v1);
        red_add_f2(&g_agg2[d.z], v2);
        red_add_f2(&g_agg2[d.w], v3);
    } else {
        cudaGridDependencySynchronize();
    }
}

__global__ void k_out(const float* __restrict__ b2, float2* __restrict__ out2) {
    cudaTriggerProgrammaticLaunchCompletion();
    int i = blockIdx.x * blockDim.x + threadIdx.x;
    float bx = __ldg(&b2[0]), by = __ldg(&b2[1]); // inputs: independent
    cudaGridDependencySynchronize();              // wait for k_scatter2
    if (i >= N_NODES) return;
    float di = g_dinv[i];
    float2 t = g_agg2[i];
    float zx = t.x * di + bx;
    float zy = t.y * di + by;
    float m = fmaxf(zx, zy);
    float l = m + __logf(__expf(zx - m) + __expf(zy - m));
    out2[i] = make_float2(zx - l, zy - l);
}

// ---------------------------------------------------------------------------
extern "C" void kernel_launch(void* const* d_in, const int* in_sizes, int n_in,
                              void* d_out, int out_size) {
    const float* x  = (const float*)d_in[0];   // [N,2]
    const int*   ei = (const int*)d_in[1];     // [2,E] int32
    const float* W1 = (const float*)d_in[2];
    const float* b1 = (const float*)d_in[3];
    const float* W2 = (const float*)d_in[4];
    const float* b2 = (const float*)d_in[5];

    const int4* src4 = (const int4*)ei;
    const int4* dst4 = (const int4*)(ei + N_EDGES);
    const float2* x2 = (const float2*)x;
    const float4* W1v = (const float4*)W1;
    const float4* b1v = (const float4*)b1;
    const float4* W2v = (const float4*)W2;
    float2* out2 = (float2*)d_out;

    const int T = 256;
    const int gN  = (N_NODES + T - 1) / T;
    const int gE4 = (E4 + T - 1) / T;

    cudaLaunchAttribute attr;
    attr.id = cudaLaunchAttributeProgrammaticStreamSerialization;
    attr.val.programmaticStreamSerializationAllowed = 1;

    cudaLaunchConfig_t cfg = {};
    cfg.blockDim = dim3(T, 1, 1);
    cfg.dynamicSmemBytes = 0;
    cfg.stream = 0;
    cfg.attrs = &attr;
    cfg.numAttrs = 1;

    // First node: plain launch (no intra-graph predecessor).
    k_degree<<<gE4, T>>>(dst4);

    cfg.gridDim = dim3(gN, 1, 1);
    cudaLaunchKernelEx(&cfg, k_pre1, x2);

    cfg.gridDim = dim3(gE4, 1, 1);
    cudaLaunchKernelEx(&cfg, k_scatter1, src4, dst4);

    cfg.gridDim = dim3(gN, 1, 1);
    cudaLaunchKernelEx(&cfg, k_mid, W1v, b1v, W2v);

    cfg.gridDim = dim3(gE4, 1, 1);
    cudaLaunchKernelEx(&cfg, k_scatter2, src4, dst4);

    cfg.gridDim = dim3(gN, 1, 1);
    cudaLaunchKernelEx(&cfg, k_out, b2, out2);
}